// round 4
// baseline (speedup 1.0000x reference)
#include <cuda_runtime.h>
#include <cuda_fp16.h>

#define PP 32
#define SS 4
#define HH 256
#define WW 256
#define HW (HH*WW)          // 65536
#define NPIX (SS*HW)        // 262144
#define NOUT (PP*SS*HW)     // 8388608

// Scratch per (p,s,pixel): two half2 = {acc.r,acc.g | acc.b,T}  (8 B)
__device__ uint2 g_data[(size_t)PP * SS * HW];   // 67 MB
// Per (s,pixel): {bro.r,bro.g | bro.b,src.r | src.g,src.b | pad} (16 B, L2-resident)
__device__ uint4 g_bs[SS * HW];                  // 4 MB

static __device__ __forceinline__ unsigned pack2(float a, float b) {
    __half2 h = __floats2half2_rn(a, b);
    return *reinterpret_cast<unsigned*>(&h);
}
static __device__ __forceinline__ __half2 as_h2(unsigned u) {
    return *reinterpret_cast<__half2*>(&u);
}

// ---------------------------------------------------------------------------
// Pass 1: 32-plane alpha-compositing scan per (s,pixel); emits fp16 records.
// colors staged through smem for fully-coalesced loads.
// ---------------------------------------------------------------------------
__global__ void __launch_bounds__(256)
pass1_kernel(const float* __restrict__ colors,
             const float* __restrict__ alphas,
             const float* __restrict__ imgs_src)
{
    __shared__ float sc[768];

    const int tid = threadIdx.x;
    const int blockstart = blockIdx.x * 256;
    const int idx = blockstart + tid;            // s*HW + pix

    float a[PP];
    #pragma unroll
    for (int p = 0; p < PP; p++)
        a[p] = __ldcs(alphas + (size_t)p * NPIX + idx);

    // suffix transmittance: T[p] = prod_{j>p} (1 - a[j])
    float T[PP];
    {
        float t = 1.0f;
        #pragma unroll
        for (int p = PP - 1; p >= 0; p--) { T[p] = t; t *= (1.0f - a[p]); }
    }

    float ax = 0.f, ay = 0.f, az = 0.f;          // over after plane p
    float p1x = 0.f, p1y = 0.f, p1z = 0.f;       // over[p-1]
    float p2x = 0.f, p2y = 0.f, p2z = 0.f;       // over[p-2]

    #pragma unroll 4
    for (int p = 0; p < PP; p++) {
        // coalesced stage of this block's 768 color floats for plane p
        const float* cp = colors + ((size_t)p * NPIX + blockstart) * 3;
        __syncthreads();
        sc[tid      ] = __ldcs(cp + tid);
        sc[tid + 256] = __ldcs(cp + tid + 256);
        sc[tid + 512] = __ldcs(cp + tid + 512);
        __syncthreads();

        float cr = sc[3*tid], cg = sc[3*tid+1], cb = sc[3*tid+2];

        p2x = p1x; p2y = p1y; p2z = p1z;
        p1x = ax;  p1y = ay;  p1z = az;

        float ap  = a[p];
        float cap = 1.0f - ap;
        ax = fmaf(ax, cap, cr * ap);
        ay = fmaf(ay, cap, cg * ap);
        az = fmaf(az, cap, cb * ap);

        // acc[p] = over[max(p-2,0)]
        float sx, sy, sz;
        if (p == 0)      { sx = ax;  sy = ay;  sz = az;  }
        else if (p == 1) { sx = p1x; sy = p1y; sz = p1z; }
        else             { sx = p2x; sy = p2y; sz = p2z; }

        __stcs(&g_data[(size_t)p * NPIX + idx],
               make_uint2(pack2(sx, sy), pack2(sz, T[p])));
    }

    // bro = over[P-1]; pack with src image
    const float* sp = imgs_src + (size_t)idx * 3;
    float s0 = __ldg(sp + 0), s1 = __ldg(sp + 1), s2 = __ldg(sp + 2);
    g_bs[idx] = make_uint4(pack2(ax, ay), pack2(az, s0), pack2(s1, s2), 0u);
}

// ---------------------------------------------------------------------------
// Pass 2: per-(p,s) warp + bilinear gather (half2 accumulate) + write.
// One block = 256 consecutive pixels of one (p,s); thread 0 builds the
// 12 warp coefficients (K_src @ R @ K_tgt^-1 * d  |  K_src @ t).
// ---------------------------------------------------------------------------
__global__ void __launch_bounds__(256)
pass2_kernel(const float* __restrict__ mpi_planes,
             const float* __restrict__ pose_tgt,
             const float* __restrict__ intrins_src,
             const float* __restrict__ intrins_tgt,
             float* __restrict__ out)
{
    __shared__ float w[12];

    int b   = blockIdx.x;
    int ps  = b >> 8;                         // 256 blocks per (p,s)
    int pix = ((b & 255) << 8) + threadIdx.x;
    int s   = ps & (SS - 1);
    int p   = ps >> 2;

    if (threadIdx.x == 0) {
        float Kt[9];
        #pragma unroll
        for (int i = 0; i < 9; i++) Kt[i] = intrins_tgt[i];
        float det = Kt[0]*(Kt[4]*Kt[8]-Kt[5]*Kt[7])
                  - Kt[1]*(Kt[3]*Kt[8]-Kt[5]*Kt[6])
                  + Kt[2]*(Kt[3]*Kt[7]-Kt[4]*Kt[6]);
        float id = 1.0f / det;
        float inv[9];
        inv[0]=(Kt[4]*Kt[8]-Kt[5]*Kt[7])*id;
        inv[1]=(Kt[2]*Kt[7]-Kt[1]*Kt[8])*id;
        inv[2]=(Kt[1]*Kt[5]-Kt[2]*Kt[4])*id;
        inv[3]=(Kt[5]*Kt[6]-Kt[3]*Kt[8])*id;
        inv[4]=(Kt[0]*Kt[8]-Kt[2]*Kt[6])*id;
        inv[5]=(Kt[2]*Kt[3]-Kt[0]*Kt[5])*id;
        inv[6]=(Kt[3]*Kt[7]-Kt[4]*Kt[6])*id;
        inv[7]=(Kt[1]*Kt[6]-Kt[0]*Kt[7])*id;
        inv[8]=(Kt[0]*Kt[4]-Kt[1]*Kt[3])*id;

        const float* Ks   = intrins_src + s * 9;
        const float* pose = pose_tgt   + s * 16;

        float A[9], bb[3];
        #pragma unroll
        for (int i = 0; i < 3; i++) {
            #pragma unroll
            for (int j = 0; j < 3; j++) {
                float acc = 0.f;
                #pragma unroll
                for (int k = 0; k < 3; k++) acc += Ks[i*3+k] * pose[k*4+j];
                A[i*3+j] = acc;
            }
            float accb = 0.f;
            #pragma unroll
            for (int k = 0; k < 3; k++) accb += Ks[i*3+k] * pose[k*4+3];
            bb[i] = accb;
        }
        float d = mpi_planes[p];
        #pragma unroll
        for (int i = 0; i < 3; i++)
            #pragma unroll
            for (int j = 0; j < 3; j++) {
                float acc = 0.f;
                #pragma unroll
                for (int k = 0; k < 3; k++) acc += A[i*3+k] * inv[k*3+j];
                w[i*3+j] = acc * d;
            }
        w[9] = bb[0]; w[10] = bb[1]; w[11] = bb[2];
    }
    __syncthreads();

    float fx = (float)(pix & (WW - 1));
    float fy = (float)(pix >> 8);

    float u0 = fmaf(w[0], fx, fmaf(w[1], fy, w[2])) + w[9];
    float u1 = fmaf(w[3], fx, fmaf(w[4], fy, w[5])) + w[10];
    float u2 = fmaf(w[6], fx, fmaf(w[7], fy, w[8])) + w[11];
    float z  = u2 + 1e-10f;
    float ix = u0 / z;
    float iy = u1 / z;

    float x0f = floorf(ix), y0f = floorf(iy);
    float wx1 = ix - x0f, wy1 = iy - y0f;
    float wx0 = 1.0f - wx1, wy0 = 1.0f - wy1;

    const size_t basep = (size_t)ps * HW;   // this (p,s) plane in g_data
    const int    bases = s * HW;            // bro/src slice

    __half2 acc0 = __float2half2_rn(0.f);   // {acc.r, acc.g}
    __half2 acc1 = acc0;                    // {acc.b, T}
    __half2 acc2 = acc0;                    // {bro.r, bro.g}
    __half2 acc3 = acc0;                    // {bro.b, src.r}
    __half2 acc4 = acc0;                    // {src.g, src.b}

    #pragma unroll
    for (int cy = 0; cy < 2; cy++) {
        float yyf = y0f + (float)cy;
        float wy  = cy ? wy1 : wy0;
        #pragma unroll
        for (int cx = 0; cx < 2; cx++) {
            float xxf = x0f + (float)cx;
            bool valid = (xxf >= 0.f) & (xxf <= (float)(WW - 1)) &
                         (yyf >= 0.f) & (yyf <= (float)(HH - 1));
            if (!valid) continue;
            float wgt = (cx ? wx1 : wx0) * wy;
            int off = (int)yyf * WW + (int)xxf;

            uint2 dU = __ldg(&g_data[basep + off]);
            uint4 bU = __ldg(&g_bs[bases + off]);

            __half2 hw = __float2half2_rn(wgt);
            acc0 = __hfma2(as_h2(dU.x), hw, acc0);
            acc1 = __hfma2(as_h2(dU.y), hw, acc1);
            acc2 = __hfma2(as_h2(bU.x), hw, acc2);
            acc3 = __hfma2(as_h2(bU.y), hw, acc3);
            acc4 = __hfma2(as_h2(bU.z), hw, acc4);
        }
    }

    float2 f0 = __half22float2(acc0);
    float2 f1 = __half22float2(acc1);
    float2 f2 = __half22float2(acc2);
    float2 f3 = __half22float2(acc3);
    float2 f4 = __half22float2(acc4);

    float* op = out + (size_t)ps * 10 * HW + pix;
    __stcs(op + 0*HW, f1.y);   // T
    __stcs(op + 1*HW, f0.x);   // acc.r
    __stcs(op + 2*HW, f0.y);   // acc.g
    __stcs(op + 3*HW, f1.x);   // acc.b
    __stcs(op + 4*HW, f2.x);   // bro.r
    __stcs(op + 5*HW, f2.y);   // bro.g
    __stcs(op + 6*HW, f3.x);   // bro.b
    __stcs(op + 7*HW, f3.y);   // src.r
    __stcs(op + 8*HW, f4.x);   // src.g
    __stcs(op + 9*HW, f4.y);   // src.b
}

// ---------------------------------------------------------------------------
extern "C" void kernel_launch(void* const* d_in, const int* in_sizes, int n_in,
                              void* d_out, int out_size)
{
    const float* colors      = (const float*)d_in[0];  // (P,S,H,W,3)
    const float* alphas      = (const float*)d_in[1];  // (P,S,H,W)
    const float* imgs_src    = (const float*)d_in[2];  // (S,H,W,3)
    const float* mpi_planes  = (const float*)d_in[3];  // (P,)
    const float* pose_tgt    = (const float*)d_in[4];  // (S,4,4)
    const float* intrins_src = (const float*)d_in[5];  // (S,3,3)
    const float* intrins_tgt = (const float*)d_in[6];  // (3,3)
    float* out = (float*)d_out;                        // (P,S,10,H,W)

    pass1_kernel<<<NPIX / 256, 256>>>(colors, alphas, imgs_src);
    pass2_kernel<<<NOUT / 256, 256>>>(mpi_planes, pose_tgt,
                                      intrins_src, intrins_tgt, out);
}

// round 5
// speedup vs baseline: 1.2232x; 1.2232x over previous
#include <cuda_runtime.h>
#include <cuda_fp16.h>

#define PP 32
#define SS 4
#define HH 256
#define WW 256
#define HW (HH*WW)          // 65536
#define NPIX (SS*HW)        // 262144
#define NOUT (PP*SS*HW)     // 8388608

// Scratch per (p,s,pixel): two half2 = {acc.r,acc.g | acc.b,T}  (8 B)
__device__ uint2 g_data[(size_t)PP * SS * HW];   // 67 MB
// Per (s,pixel): {bro.r,bro.g | bro.b,src.r | src.g,src.b | pad} (16 B, L2-resident)
__device__ uint4 g_bs[SS * HW];                  // 4 MB

static __device__ __forceinline__ unsigned pack2(float a, float b) {
    __half2 h = __floats2half2_rn(a, b);
    return *reinterpret_cast<unsigned*>(&h);
}
static __device__ __forceinline__ __half2 as_h2(unsigned u) {
    return *reinterpret_cast<__half2*>(&u);
}

// ---------------------------------------------------------------------------
// Pass 1: 32-plane alpha-compositing scan per (s,pixel); emits fp16 records.
// (R3 form: direct stride-3 color loads, NO smem staging / barriers.)
// ---------------------------------------------------------------------------
__global__ void __launch_bounds__(256)
pass1_kernel(const float* __restrict__ colors,
             const float* __restrict__ alphas,
             const float* __restrict__ imgs_src)
{
    int idx = blockIdx.x * blockDim.x + threadIdx.x;   // s*HW + pix
    if (idx >= NPIX) return;

    float a[PP];
    #pragma unroll
    for (int p = 0; p < PP; p++)
        a[p] = __ldcs(alphas + (size_t)p * NPIX + idx);

    // suffix transmittance: T[p] = prod_{j>p} (1 - a[j])
    float T[PP];
    {
        float t = 1.0f;
        #pragma unroll
        for (int p = PP - 1; p >= 0; p--) { T[p] = t; t *= (1.0f - a[p]); }
    }

    float ax = 0.f, ay = 0.f, az = 0.f;          // over after plane p
    float p1x = 0.f, p1y = 0.f, p1z = 0.f;       // over[p-1]
    float p2x = 0.f, p2y = 0.f, p2z = 0.f;       // over[p-2]

    #pragma unroll
    for (int p = 0; p < PP; p++) {
        p2x = p1x; p2y = p1y; p2z = p1z;
        p1x = ax;  p1y = ay;  p1z = az;

        const float* c = colors + ((size_t)p * NPIX + idx) * 3;
        float ap  = a[p];
        float cap = 1.0f - ap;
        ax = fmaf(ax, cap, __ldcs(c + 0) * ap);
        ay = fmaf(ay, cap, __ldcs(c + 1) * ap);
        az = fmaf(az, cap, __ldcs(c + 2) * ap);

        // acc[p] = over[max(p-2,0)]
        float sx, sy, sz;
        if (p == 0)      { sx = ax;  sy = ay;  sz = az;  }
        else if (p == 1) { sx = p1x; sy = p1y; sz = p1z; }
        else             { sx = p2x; sy = p2y; sz = p2z; }

        __stcs(&g_data[(size_t)p * NPIX + idx],
               make_uint2(pack2(sx, sy), pack2(sz, T[p])));
    }

    // bro = over[P-1]; pack with src image
    const float* sp = imgs_src + (size_t)idx * 3;
    float s0 = __ldg(sp + 0), s1 = __ldg(sp + 1), s2 = __ldg(sp + 2);
    g_bs[idx] = make_uint4(pack2(ax, ay), pack2(az, s0), pack2(s1, s2), 0u);
}

// ---------------------------------------------------------------------------
// Pass 2: per-(p,s) warp + bilinear gather + write (P,S,10,H,W).
// 4 pixels per thread (stride 256 = same x, consecutive y) for MLP/ILP.
// One block = 1024 pixels of one (p,s); thread 0 builds 12 warp coeffs.
// ---------------------------------------------------------------------------
__global__ void __launch_bounds__(256)
pass2_kernel(const float* __restrict__ mpi_planes,
             const float* __restrict__ pose_tgt,
             const float* __restrict__ intrins_src,
             const float* __restrict__ intrins_tgt,
             float* __restrict__ out)
{
    __shared__ float w[12];

    int b    = blockIdx.x;
    int ps   = b >> 6;                        // 64 blocks per (p,s)
    int pix0 = ((b & 63) << 10) + threadIdx.x;
    int s    = ps & (SS - 1);
    int p    = ps >> 2;

    if (threadIdx.x == 0) {
        float Kt[9];
        #pragma unroll
        for (int i = 0; i < 9; i++) Kt[i] = intrins_tgt[i];
        float det = Kt[0]*(Kt[4]*Kt[8]-Kt[5]*Kt[7])
                  - Kt[1]*(Kt[3]*Kt[8]-Kt[5]*Kt[6])
                  + Kt[2]*(Kt[3]*Kt[7]-Kt[4]*Kt[6]);
        float id = 1.0f / det;
        float inv[9];
        inv[0]=(Kt[4]*Kt[8]-Kt[5]*Kt[7])*id;
        inv[1]=(Kt[2]*Kt[7]-Kt[1]*Kt[8])*id;
        inv[2]=(Kt[1]*Kt[5]-Kt[2]*Kt[4])*id;
        inv[3]=(Kt[5]*Kt[6]-Kt[3]*Kt[8])*id;
        inv[4]=(Kt[0]*Kt[8]-Kt[2]*Kt[6])*id;
        inv[5]=(Kt[2]*Kt[3]-Kt[0]*Kt[5])*id;
        inv[6]=(Kt[3]*Kt[7]-Kt[4]*Kt[6])*id;
        inv[7]=(Kt[1]*Kt[6]-Kt[0]*Kt[7])*id;
        inv[8]=(Kt[0]*Kt[4]-Kt[1]*Kt[3])*id;

        const float* Ks   = intrins_src + s * 9;
        const float* pose = pose_tgt   + s * 16;

        float A[9], bb[3];
        #pragma unroll
        for (int i = 0; i < 3; i++) {
            #pragma unroll
            for (int j = 0; j < 3; j++) {
                float acc = 0.f;
                #pragma unroll
                for (int k = 0; k < 3; k++) acc += Ks[i*3+k] * pose[k*4+j];
                A[i*3+j] = acc;
            }
            float accb = 0.f;
            #pragma unroll
            for (int k = 0; k < 3; k++) accb += Ks[i*3+k] * pose[k*4+3];
            bb[i] = accb;
        }
        float d = mpi_planes[p];
        #pragma unroll
        for (int i = 0; i < 3; i++)
            #pragma unroll
            for (int j = 0; j < 3; j++) {
                float acc = 0.f;
                #pragma unroll
                for (int k = 0; k < 3; k++) acc += A[i*3+k] * inv[k*3+j];
                w[i*3+j] = acc * d;
            }
        w[9] = bb[0]; w[10] = bb[1]; w[11] = bb[2];
    }
    __syncthreads();

    const size_t basep = (size_t)ps * HW;
    const int    bases = s * HW;
    float*       op    = out + (size_t)ps * 10 * HW;

    const float fx = (float)(pix0 & (WW - 1));
    const float fy0 = (float)(pix0 >> 8);

    // Accumulators for 4 pixels x 5 half2 channels
    __half2 acc[4][5];
    #pragma unroll
    for (int k = 0; k < 4; k++)
        #pragma unroll
        for (int c = 0; c < 5; c++)
            acc[k][c] = __float2half2_rn(0.f);

    #pragma unroll
    for (int k = 0; k < 4; k++) {
        float fy = fy0 + (float)k;
        float u0 = fmaf(w[0], fx, fmaf(w[1], fy, w[2])) + w[9];
        float u1 = fmaf(w[3], fx, fmaf(w[4], fy, w[5])) + w[10];
        float u2 = fmaf(w[6], fx, fmaf(w[7], fy, w[8])) + w[11];
        float z  = u2 + 1e-10f;
        float ix = u0 / z;
        float iy = u1 / z;

        float x0f = floorf(ix), y0f = floorf(iy);
        float wx1 = ix - x0f, wy1 = iy - y0f;
        float wx0 = 1.0f - wx1, wy0 = 1.0f - wy1;

        #pragma unroll
        for (int cy = 0; cy < 2; cy++) {
            float yyf = y0f + (float)cy;
            float wy  = cy ? wy1 : wy0;
            #pragma unroll
            for (int cx = 0; cx < 2; cx++) {
                float xxf = x0f + (float)cx;
                bool valid = (xxf >= 0.f) & (xxf <= (float)(WW - 1)) &
                             (yyf >= 0.f) & (yyf <= (float)(HH - 1));
                if (!valid) continue;
                float wgt = (cx ? wx1 : wx0) * wy;
                int off = (int)yyf * WW + (int)xxf;

                uint2 dU = __ldg(&g_data[basep + off]);
                uint4 bU = __ldg(&g_bs[bases + off]);

                __half2 hw = __float2half2_rn(wgt);
                acc[k][0] = __hfma2(as_h2(dU.x), hw, acc[k][0]);
                acc[k][1] = __hfma2(as_h2(dU.y), hw, acc[k][1]);
                acc[k][2] = __hfma2(as_h2(bU.x), hw, acc[k][2]);
                acc[k][3] = __hfma2(as_h2(bU.y), hw, acc[k][3]);
                acc[k][4] = __hfma2(as_h2(bU.z), hw, acc[k][4]);
            }
        }
    }

    #pragma unroll
    for (int k = 0; k < 4; k++) {
        int pix = pix0 + (k << 8);
        float2 f0 = __half22float2(acc[k][0]);
        float2 f1 = __half22float2(acc[k][1]);
        float2 f2 = __half22float2(acc[k][2]);
        float2 f3 = __half22float2(acc[k][3]);
        float2 f4 = __half22float2(acc[k][4]);

        __stcs(op + 0*HW + pix, f1.y);   // T
        __stcs(op + 1*HW + pix, f0.x);   // acc.r
        __stcs(op + 2*HW + pix, f0.y);   // acc.g
        __stcs(op + 3*HW + pix, f1.x);   // acc.b
        __stcs(op + 4*HW + pix, f2.x);   // bro.r
        __stcs(op + 5*HW + pix, f2.y);   // bro.g
        __stcs(op + 6*HW + pix, f3.x);   // bro.b
        __stcs(op + 7*HW + pix, f3.y);   // src.r
        __stcs(op + 8*HW + pix, f4.x);   // src.g
        __stcs(op + 9*HW + pix, f4.y);   // src.b
    }
}

// ---------------------------------------------------------------------------
extern "C" void kernel_launch(void* const* d_in, const int* in_sizes, int n_in,
                              void* d_out, int out_size)
{
    const float* colors      = (const float*)d_in[0];  // (P,S,H,W,3)
    const float* alphas      = (const float*)d_in[1];  // (P,S,H,W)
    const float* imgs_src    = (const float*)d_in[2];  // (S,H,W,3)
    const float* mpi_planes  = (const float*)d_in[3];  // (P,)
    const float* pose_tgt    = (const float*)d_in[4];  // (S,4,4)
    const float* intrins_src = (const float*)d_in[5];  // (S,3,3)
    const float* intrins_tgt = (const float*)d_in[6];  // (3,3)
    float* out = (float*)d_out;                        // (P,S,10,H,W)

    pass1_kernel<<<NPIX / 256, 256>>>(colors, alphas, imgs_src);
    pass2_kernel<<<NOUT / 1024, 256>>>(mpi_planes, pose_tgt,
                                       intrins_src, intrins_tgt, out);
}